// round 15
// baseline (speedup 1.0000x reference)
#include <cuda_runtime.h>
#include <cuda_fp16.h>
#include <cstdint>

#define HW 1024
#define CDIM 256
#define NSIDE 8192
#define NTOT 16384

// -------- scratch (device globals; no allocation allowed) --------
__device__ __half g_Xh[NTOT * CDIM];      // x transposed to [n][c], fp16
__device__ __half g_Whqk[512 * CDIM];     // [wq;wk] as [o][c], fp16
__device__ __half g_Qh[NTOT * CDIM];
__device__ __half g_Kh[NTOT * CDIM];
__device__ float  g_wcT[CDIM * 128];      // (w128 @ wv) transposed [c][o]
__device__ float  g_pb2[128];             // w128 @ bv
__device__ float  g_BM[NTOT * 16];
__device__ float  g_GW[4 * NSIDE];
__device__ float  g_P[128 * NTOT];

// ======================= helpers =======================
__device__ __forceinline__ uint32_t smem_u32(const void* p) {
    uint32_t a;
    asm("{ .reg .u64 t; cvta.to.shared.u64 t, %1; cvt.u32.u64 %0, t; }"
        : "=r"(a) : "l"(p));
    return a;
}
__device__ __forceinline__ void cp_async16(uint32_t dst, const void* src) {
    asm volatile("cp.async.cg.shared.global [%0], [%1], 16;" :: "r"(dst), "l"(src) : "memory");
}
#define CP_COMMIT() asm volatile("cp.async.commit_group;" ::: "memory")
#define CP_WAIT(n)  asm volatile("cp.async.wait_group %0;" :: "n"(n) : "memory")

__device__ __forceinline__ void mma_fp16(float* c, const uint32_t* a,
                                         uint32_t b0, uint32_t b1) {
    asm volatile(
        "mma.sync.aligned.m16n8k16.row.col.f32.f16.f16.f32 "
        "{%0,%1,%2,%3}, {%4,%5,%6,%7}, {%8,%9}, {%0,%1,%2,%3};"
        : "+f"(c[0]), "+f"(c[1]), "+f"(c[2]), "+f"(c[3])
        : "r"(a[0]), "r"(a[1]), "r"(a[2]), "r"(a[3]), "r"(b0), "r"(b1));
}
__device__ __forceinline__ void ldsm_x4(uint32_t* r, uint32_t addr) {
    asm volatile("ldmatrix.sync.aligned.m8n8.x4.shared.b16 {%0,%1,%2,%3}, [%4];"
        : "=r"(r[0]), "=r"(r[1]), "=r"(r[2]), "=r"(r[3]) : "r"(addr));
}

// ===========================================================================
// wcombT[c][o] = sum_k w128[o][k] * wv[k][c]
// ===========================================================================
__global__ void combine_w_kernel(const float* __restrict__ w128,
                                 const float* __restrict__ wv) {
    int c = blockIdx.x, o = threadIdx.x;
    float s = 0.f;
    #pragma unroll 8
    for (int k = 0; k < 256; k++)
        s += w128[o * 256 + k] * wv[k * 256 + c];
    g_wcT[c * 128 + o] = s;
}

__global__ void pb2_kernel(const float* __restrict__ w128,
                           const float* __restrict__ bv) {
    int o = threadIdx.x;
    float s = 0.f;
    #pragma unroll 8
    for (int c = 0; c < 256; c++) s += w128[o * 256 + c] * bv[c];
    g_pb2[o] = s;
}

// ===========================================================================
// Merged converts: z<16 -> x [b][c][hw] -> g_Xh [n][c] fp16 (tiled transpose)
//                  z==16 -> wq/wk -> fp16 [o][c]
// ===========================================================================
__global__ void convert_kernel(const float* __restrict__ x4,
                               const float* __restrict__ x3,
                               const float* __restrict__ wq,
                               const float* __restrict__ wk) {
    int z = blockIdx.z;
    int t = threadIdx.x;
    if (z == 16) {
        int bid = blockIdx.y * 32 + blockIdx.x;   // 0..255
        int e = bid * 512 + t;
        #pragma unroll
        for (int i = 0; i < 2; i++, e += 256) {
            int o = e >> 8, cc = e & 255;
            float v = (o < 256) ? wq[o * 256 + cc] : wk[(o - 256) * 256 + cc];
            g_Whqk[e] = __float2half_rn(v);
        }
        return;
    }
    __shared__ float tile[32][33];
    int side = z >> 3, b = z & 7;
    const float* x = (side ? x3 : x4) + b * CDIM * HW;
    int hw0 = blockIdx.x * 32;
    int c0 = blockIdx.y * 32;
    int lane = t & 31, ty = t >> 5;

    #pragma unroll
    for (int i = 0; i < 4; i++) {
        int cc = ty + i * 8;
        tile[cc][lane] = x[(c0 + cc) * HW + hw0 + lane];
    }
    __syncthreads();
    int nbase = side * NSIDE + b * HW + hw0;
    #pragma unroll
    for (int i = 0; i < 4; i++) {
        int hwr = ty + i * 8;
        g_Xh[(nbase + hwr) * 256 + c0 + lane] = __float2half_rn(tile[lane][hwr]);
    }
}

// ===========================================================================
// QK fp16 tensor GEMM, 128x64 CTA tile, 2 CTAs/SM.
// ===========================================================================
#define QKG_SMEM ((128 + 64) * 264 * 2)   // 101376 B

__global__ void __launch_bounds__(256, 2) qk_gemm_kernel(const float* __restrict__ bq,
                                                         const float* __restrict__ bk) {
    extern __shared__ __half smh[];
    __half* Xs = smh;                 // 128 x 264
    __half* Ws = smh + 128 * 264;     // 64 x 264
    int t = threadIdx.x, lane = t & 31, wid = t >> 5;
    int wm = wid >> 1, wn = wid & 1;
    int grp = lane >> 2, qid = lane & 3;
    int m0 = blockIdx.x * 128;
    int ob = blockIdx.y;

    uint32_t xb = smem_u32(Xs), wb = smem_u32(Ws);
    #pragma unroll
    for (int i = 0; i < 24; i++) {
        int s = t + i * 256;
        int row = s >> 5, seg = s & 31;
        if (row < 128)
            cp_async16(xb + row * 528 + seg * 16,
                       (const char*)&g_Xh[(size_t)(m0 + row) * 256] + seg * 16);
        else
            cp_async16(wb + (row - 128) * 528 + seg * 16,
                       (const char*)&g_Whqk[(size_t)(ob * 64 + row - 128) * 256] + seg * 16);
    }
    CP_COMMIT(); CP_WAIT(0);
    __syncthreads();

    float acc[2][4][4] = {};
    #pragma unroll
    for (int kk = 0; kk < 16; kk++) {
        uint32_t a[2][4];
        #pragma unroll
        for (int rt = 0; rt < 2; rt++) {
            const __half* q0 = &Xs[(wm * 32 + rt * 16 + grp) * 264 + kk * 16 + qid * 2];
            a[rt][0] = *(const uint32_t*)q0;
            a[rt][1] = *(const uint32_t*)(q0 + 8 * 264);
            a[rt][2] = *(const uint32_t*)(q0 + 8);
            a[rt][3] = *(const uint32_t*)(q0 + 8 * 264 + 8);
        }
        #pragma unroll
        for (int nt = 0; nt < 4; nt++) {
            const __half* kp = &Ws[(wn * 32 + nt * 8 + grp) * 264 + kk * 16 + qid * 2];
            uint32_t b0 = *(const uint32_t*)kp;
            uint32_t b1 = *(const uint32_t*)(kp + 8);
            #pragma unroll
            for (int rt = 0; rt < 2; rt++)
                mma_fp16(acc[rt][nt], a[rt], b0, b1);
        }
    }

    bool isQ = (ob < 4);
    __half* dst = isQ ? g_Qh : g_Kh;
    const float* bias = isQ ? bq : bk;
    #pragma unroll
    for (int rt = 0; rt < 2; rt++)
        #pragma unroll
        for (int nt = 0; nt < 4; nt++) {
            int col = (ob & 3) * 64 + wn * 32 + nt * 8 + qid * 2;
            float b0f = bias[col], b1f = bias[col + 1];
            int r0 = m0 + wm * 32 + rt * 16 + grp;
            __half2 h0 = __floats2half2_rn(acc[rt][nt][0] + b0f, acc[rt][nt][1] + b1f);
            __half2 h1 = __floats2half2_rn(acc[rt][nt][2] + b0f, acc[rt][nt][3] + b1f);
            *(__half2*)&dst[(size_t)r0 * 256 + col] = h0;
            *(__half2*)&dst[(size_t)(r0 + 8) * 256 + col] = h1;
        }
}

// ===========================================================================
// fp16 tensor-core S block-max: 4 warps, warp tile 64x64; pair-scoped K
// loading + named pair barriers (unchanged from R14 — proven).
// ===========================================================================
#define SMAX_SMEM (65536 + 3 * 16384)   // 114688 B -> 2 CTAs/SM

__device__ __forceinline__ void load_k_half(uint32_t kb, int jbase, int c,
                                            int wc, int pt) {
    int jc = c >> 2, kc = c & 3;
    const __half* src = &g_Kh[(size_t)(jbase + jc * 128) * 256 + kc * 64];
    #pragma unroll
    for (int i = 0; i < 8; i++) {
        int idx = pt + i * 64;            // 512 16B segments per half
        int row = wc * 64 + (idx >> 3), seg = idx & 7;
        cp_async16(kb + (uint32_t)(row * 128 + ((seg ^ (row & 7)) * 16)),
                   (const char*)(src + row * 256) + seg * 16);
    }
    CP_COMMIT();
}

__global__ void __launch_bounds__(128, 2) smax_kernel() {
    extern __shared__ char sm[];
    uint32_t qbase = smem_u32(sm);
    uint32_t kbase = qbase + 65536;
    float* red = (float*)(sm + 65536);    // overlaps buffers (used after loop)

    int t = threadIdx.x, lane = t & 31, wid = t >> 5;
    int wr = wid >> 1, wc = wid & 1;      // 2 row-groups x 2 key-halves
    int grp = lane >> 2, qid = lane & 3;
    int pt = wr * 32 + lane;              // index within pair [0,64)
    int i0 = blockIdx.x * 128, kb = blockIdx.y, jbase = kb * HW;

    // Q tile -> smem, swizzled (all threads), then pair K-half prologue
    #pragma unroll
    for (int i = 0; i < 32; i++) {
        int idx = t + i * 128;
        int row = idx >> 5, seg = idx & 31;
        int seg2 = (seg & 24) | ((seg & 7) ^ (row & 7));
        cp_async16(qbase + (uint32_t)(row * 512 + seg2 * 16),
                   (const char*)&g_Qh[(size_t)(i0 + row) * 256] + seg * 16);
    }
    CP_COMMIT();
    load_k_half(kbase + 0 * 16384, jbase, 0, wc, pt);
    load_k_half(kbase + 1 * 16384, jbase, 1, wc, pt);
    CP_WAIT(2);            // Q complete for this thread
    __syncthreads();       // Q complete CTA-wide

    int sw = lane & 7;
    int hi = lane >> 4;
    int lo8 = (lane >> 3) & 1;
    uint32_t qbA = qbase + (uint32_t)((wr * 64 + (lane & 15)) * 512);
    uint32_t kbB = (uint32_t)((wc * 64 + hi * 8 + sw) * 128);
    uint32_t offA[4], offB[4];
    #pragma unroll
    for (int s = 0; s < 4; s++) {
        offA[s] = (uint32_t)(((s * 2 + hi) ^ sw) * 16);
        offB[s] = (uint32_t)(((s * 2 + lo8) ^ sw) * 16);
    }

    float rmax[4][2] = {{-1e30f, -1e30f}, {-1e30f, -1e30f},
                        {-1e30f, -1e30f}, {-1e30f, -1e30f}};
    float acc[4][8][4];
    int barid = 1 + wc;

    for (int c = 0; c < 32; c++) {
        if (c < 31) { CP_WAIT(1); } else { CP_WAIT(0); }
        asm volatile("bar.sync %0, 64;" :: "r"(barid) : "memory");
        if (c + 2 < 32)
            load_k_half(kbase + (uint32_t)((c + 2) % 3) * 16384, jbase, c + 2, wc, pt);

        int kc = c & 3;
        uint32_t kbuf = kbase + (uint32_t)(c % 3) * 16384 + kbB;
        uint32_t qA = qbA + (uint32_t)(kc * 128);

        if (kc == 0) {
            #pragma unroll
            for (int rt = 0; rt < 4; rt++)
                #pragma unroll
                for (int nt = 0; nt < 8; nt++)
                    #pragma unroll
                    for (int r = 0; r < 4; r++) acc[rt][nt][r] = 0.f;
        }

        #pragma unroll
        for (int s = 0; s < 4; s++) {
            uint32_t a[4][4];
            #pragma unroll
            for (int rt = 0; rt < 4; rt++)
                ldsm_x4(a[rt], qA + (uint32_t)(rt * 8192) + offA[s]);
            #pragma unroll
            for (int nt2 = 0; nt2 < 4; nt2++) {
                uint32_t bquad[4];
                ldsm_x4(bquad, kbuf + (uint32_t)(nt2 * 2048) + offB[s]);
                #pragma unroll
                for (int rt = 0; rt < 4; rt++) {
                    mma_fp16(acc[rt][nt2 * 2 + 0], a[rt], bquad[0], bquad[1]);
                    mma_fp16(acc[rt][nt2 * 2 + 1], a[rt], bquad[2], bquad[3]);
                }
            }
        }

        if (kc == 3) {
            #pragma unroll
            for (int rt = 0; rt < 4; rt++)
                #pragma unroll
                for (int nt = 0; nt < 8; nt++) {
                    rmax[rt][0] = fmaxf(rmax[rt][0], fmaxf(acc[rt][nt][0], acc[rt][nt][1]));
                    rmax[rt][1] = fmaxf(rmax[rt][1], fmaxf(acc[rt][nt][2], acc[rt][nt][3]));
                }
        }
    }

    #pragma unroll
    for (int rt = 0; rt < 4; rt++)
        #pragma unroll
        for (int h = 0; h < 2; h++) {
            float v = rmax[rt][h];
            v = fmaxf(v, __shfl_xor_sync(0xFFFFFFFF, v, 1));
            v = fmaxf(v, __shfl_xor_sync(0xFFFFFFFF, v, 2));
            rmax[rt][h] = v;
        }

    __syncthreads();     // all pairs done with buffers before red overlay
    if (qid == 0) {
        #pragma unroll
        for (int rt = 0; rt < 4; rt++)
            #pragma unroll
            for (int h = 0; h < 2; h++) {
                int row = wr * 64 + rt * 16 + h * 8 + grp;
                red[wc * 128 + row] = rmax[rt][h];
            }
    }
    __syncthreads();
    if (t < 128)
        g_BM[(i0 + t) * 16 + kb] = fmaxf(red[t], red[128 + t]);
}

// ===========================================================================
// Gate: softmax over 1024 of mean-of-8-blockmax * scale (float4 BM reads)
// ===========================================================================
__global__ void gate_kernel() {
    int g = blockIdx.x >> 3;
    int b = blockIdx.x & 7;
    int side = (g == 0 || g == 2) ? 0 : 1;
    int kbb  = (g == 0 || g == 3) ? 0 : 8;
    int irow = side * NSIDE + b * HW;
    int t = threadIdx.x;

    float vals[4];
    #pragma unroll
    for (int r = 0; r < 4; r++) {
        int hw = t + 256 * r;
        const float4* bm = (const float4*)&g_BM[(irow + hw) * 16 + kbb];
        float4 v0 = bm[0], v1 = bm[1];
        vals[r] = ((v0.x + v0.y) + (v0.z + v0.w) + (v1.x + v1.y) + (v1.z + v1.w))
                  * (0.0625f / 8.0f);
    }
    __shared__ float red[256];
    float mx = fmaxf(fmaxf(vals[0], vals[1]), fmaxf(vals[2], vals[3]));
    red[t] = mx; __syncthreads();
    for (int s2 = 128; s2 > 0; s2 >>= 1) {
        if (t < s2) red[t] = fmaxf(red[t], red[t + s2]);
        __syncthreads();
    }
    mx = red[0]; __syncthreads();
    float sum = 0.f;
    #pragma unroll
    for (int r = 0; r < 4; r++) { vals[r] = expf(vals[r] - mx); sum += vals[r]; }
    red[t] = sum; __syncthreads();
    for (int s2 = 128; s2 > 0; s2 >>= 1) {
        if (t < s2) red[t] += red[t + s2];
        __syncthreads();
    }
    float inv = 1.f / red[0];
    #pragma unroll
    for (int r = 0; r < 4; r++)
        g_GW[g * NSIDE + b * HW + t + 256 * r] = vals[r] * inv;
}

// ===========================================================================
// Fused projection: P[o][n] = sum_c wcT[c][o] * x[.][c][hw] + pb2[o]
// 128(n) x 128(o) CTA tile, 8x8 per thread (64 FFMA / 4 LDS.128). grid 128.
// ===========================================================================
__global__ void __launch_bounds__(256) pcomb_kernel(const float* __restrict__ x4,
                                                    const float* __restrict__ x3) {
    int n0 = blockIdx.x * 128;
    int side = n0 >> 13;
    int rem = n0 & (NSIDE - 1);
    int b = rem >> 10;
    int hw0 = rem & (HW - 1);
    const float* x = (side ? x3 : x4) + b * CDIM * HW;

    __shared__ float Xs[16][128];   // [cc][nn]
    __shared__ float Ws[16][128];   // [cc][oo]
    int t = threadIdx.x;
    int tx = t & 15, ty = t >> 4;   // tx -> n group, ty -> o group
    float acc[8][8] = {};           // [o r][n c2]

    for (int c0 = 0; c0 < CDIM; c0 += 16) {
        #pragma unroll
        for (int r = 0; r < 4; r++) {
            int idx = r * 256 + t;          // 1024 float4 slots over 2 arrays
            int cc = idx >> 6;              // 0..15
            int c4 = (idx & 31) * 4;        // 0..124
            if (idx & 32)
                *(float4*)&Ws[cc][c4] = *(const float4*)&g_wcT[(c0 + cc) * 128 + c4];
            else
                *(float4*)&Xs[cc][c4] = *(const float4*)&x[(c0 + cc) * HW + hw0 + c4];
        }
        __syncthreads();
        #pragma unroll
        for (int kk = 0; kk < 16; kk++) {
            float4 o0v = *(const float4*)&Ws[kk][ty * 8];
            float4 o1v = *(const float4*)&Ws[kk][ty * 8 + 4];
            float4 n0v = *(const float4*)&Xs[kk][tx * 8];
            float4 n1v = *(const float4*)&Xs[kk][tx * 8 + 4];
            float oo[8] = {o0v.x, o0v.y, o0v.z, o0v.w, o1v.x, o1v.y, o1v.z, o1v.w};
            float nn[8] = {n0v.x, n0v.y, n0v.z, n0v.w, n1v.x, n1v.y, n1v.z, n1v.w};
            #pragma unroll
            for (int r = 0; r < 8; r++)
                #pragma unroll
                for (int c2 = 0; c2 < 8; c2++)
                    acc[r][c2] += oo[r] * nn[c2];
        }
        __syncthreads();
    }
    #pragma unroll
    for (int r = 0; r < 8; r++) {
        int o = ty * 8 + r;
        float pb = g_pb2[o];
        float4 v0, v1;
        v0.x = acc[r][0] + pb; v0.y = acc[r][1] + pb;
        v0.z = acc[r][2] + pb; v0.w = acc[r][3] + pb;
        v1.x = acc[r][4] + pb; v1.y = acc[r][5] + pb;
        v1.z = acc[r][6] + pb; v1.w = acc[r][7] + pb;
        *(float4*)&g_P[(size_t)o * NTOT + n0 + tx * 8] = v0;
        *(float4*)&g_P[(size_t)o * NTOT + n0 + tx * 8 + 4] = v1;
    }
}

// ===========================================================================
// Final: out = gate * P + b128; one thread serves the two channels sharing P.
// ===========================================================================
__global__ void final_kernel(const float* __restrict__ b128, float* __restrict__ out) {
    int idx4 = (blockIdx.x * 256 + threadIdx.x) * 4;
    int hw = idx4 & (HW - 1);
    int o = (idx4 >> 10) & 127;
    int rest = idx4 >> 17;
    int pside = rest & 1;
    int b = rest >> 1;
    int n = b * HW + hw;

    int gA = pside ? 2 : 3;
    int gB = pside ? 1 : 0;
    int brA = pside * 2, brB = pside * 2 + 1;

    float4 pv = *(const float4*)&g_P[(size_t)o * NTOT + pside * NSIDE + n];
    float4 ga = *(const float4*)&g_GW[gA * NSIDE + n];
    float4 gb = *(const float4*)&g_GW[gB * NSIDE + n];
    float bb = b128[o];

    float4 oa, ob;
    oa.x = ga.x * pv.x + bb; oa.y = ga.y * pv.y + bb;
    oa.z = ga.z * pv.z + bb; oa.w = ga.w * pv.w + bb;
    ob.x = gb.x * pv.x + bb; ob.y = gb.y * pv.y + bb;
    ob.z = gb.z * pv.z + bb; ob.w = gb.w * pv.w + bb;

    size_t obase = (size_t)b * 524288 + hw;
    *(float4*)&out[obase + (size_t)(brA * 128 + o) * 1024] = oa;
    *(float4*)&out[obase + (size_t)(brB * 128 + o) * 1024] = ob;
}

extern "C" void kernel_launch(void* const* d_in, const int* in_sizes, int n_in,
                              void* d_out, int out_size) {
    const float* x4   = (const float*)d_in[0];
    const float* x3   = (const float*)d_in[1];
    const float* wq   = (const float*)d_in[2];
    const float* bq   = (const float*)d_in[3];
    const float* wk   = (const float*)d_in[4];
    const float* bk   = (const float*)d_in[5];
    const float* wv   = (const float*)d_in[6];
    const float* bv   = (const float*)d_in[7];
    const float* w128 = (const float*)d_in[8];
    const float* b128 = (const float*)d_in[9];
    float* out = (float*)d_out;

    static cudaStream_t s2 = nullptr;
    static cudaEvent_t evFork = nullptr, evJoin = nullptr;
    if (!s2) {
        cudaFuncSetAttribute(smax_kernel,
                             cudaFuncAttributeMaxDynamicSharedMemorySize, SMAX_SMEM);
        cudaFuncSetAttribute(qk_gemm_kernel,
                             cudaFuncAttributeMaxDynamicSharedMemorySize, QKG_SMEM);
        cudaStreamCreateWithFlags(&s2, cudaStreamNonBlocking);
        cudaEventCreateWithFlags(&evFork, cudaEventDisableTiming);
        cudaEventCreateWithFlags(&evJoin, cudaEventDisableTiming);
    }

    // fork: independent projection branch runs concurrently with the QK chain
    cudaEventRecord(evFork, 0);
    cudaStreamWaitEvent(s2, evFork, 0);
    combine_w_kernel<<<256, 128, 0, s2>>>(w128, wv);
    pb2_kernel<<<1, 128, 0, s2>>>(w128, bv);
    pcomb_kernel<<<128, 256, 0, s2>>>(x4, x3);
    cudaEventRecord(evJoin, s2);

    // main chain
    convert_kernel<<<dim3(32, 8, 17), 256>>>(x4, x3, wq, wk);
    qk_gemm_kernel<<<dim3(128, 8), 256, QKG_SMEM>>>(bq, bk);
    smax_kernel<<<dim3(128, 16), 128, SMAX_SMEM>>>();
    gate_kernel<<<32, 256>>>();
    cudaStreamWaitEvent(0, evJoin, 0);
    final_kernel<<<2048, 256>>>(b128, out);
}

// round 16
// speedup vs baseline: 1.0070x; 1.0070x over previous
#include <cuda_runtime.h>
#include <cuda_fp16.h>
#include <cstdint>

#define HW 1024
#define CDIM 256
#define NSIDE 8192
#define NTOT 16384

// -------- scratch (device globals; no allocation allowed) --------
__device__ __half g_Xh[NTOT * CDIM];      // x transposed to [n][c], fp16
__device__ __half g_Whqk[512 * CDIM];     // [wq;wk] as [o][c], fp16
__device__ __half g_Qh[NTOT * CDIM];
__device__ __half g_Kh[NTOT * CDIM];
__device__ float  g_wcT[CDIM * 128];      // (w128 @ wv) transposed [c][o]
__device__ float  g_pb2[128];             // w128 @ bv
__device__ float  g_BM[NTOT * 16];
__device__ float  g_GW[4 * NSIDE];
__device__ float  g_P[128 * NTOT];

// ======================= helpers =======================
__device__ __forceinline__ uint32_t smem_u32(const void* p) {
    uint32_t a;
    asm("{ .reg .u64 t; cvta.to.shared.u64 t, %1; cvt.u32.u64 %0, t; }"
        : "=r"(a) : "l"(p));
    return a;
}
__device__ __forceinline__ void cp_async16(uint32_t dst, const void* src) {
    asm volatile("cp.async.cg.shared.global [%0], [%1], 16;" :: "r"(dst), "l"(src) : "memory");
}
#define CP_COMMIT() asm volatile("cp.async.commit_group;" ::: "memory")
#define CP_WAIT(n)  asm volatile("cp.async.wait_group %0;" :: "n"(n) : "memory")

__device__ __forceinline__ void mma_fp16(float* c, const uint32_t* a,
                                         uint32_t b0, uint32_t b1) {
    asm volatile(
        "mma.sync.aligned.m16n8k16.row.col.f32.f16.f16.f32 "
        "{%0,%1,%2,%3}, {%4,%5,%6,%7}, {%8,%9}, {%0,%1,%2,%3};"
        : "+f"(c[0]), "+f"(c[1]), "+f"(c[2]), "+f"(c[3])
        : "r"(a[0]), "r"(a[1]), "r"(a[2]), "r"(a[3]), "r"(b0), "r"(b1));
}
__device__ __forceinline__ void ldsm_x4(uint32_t* r, uint32_t addr) {
    asm volatile("ldmatrix.sync.aligned.m8n8.x4.shared.b16 {%0,%1,%2,%3}, [%4];"
        : "=r"(r[0]), "=r"(r[1]), "=r"(r[2]), "=r"(r[3]) : "r"(addr));
}

// ===========================================================================
// wcombT[c][o] = sum_k w128[o][k] * wv[k][c]
// ===========================================================================
__global__ void combine_w_kernel(const float* __restrict__ w128,
                                 const float* __restrict__ wv) {
    int c = blockIdx.x, o = threadIdx.x;
    float s = 0.f;
    #pragma unroll 8
    for (int k = 0; k < 256; k++)
        s += w128[o * 256 + k] * wv[k * 256 + c];
    g_wcT[c * 128 + o] = s;
}

__global__ void pb2_kernel(const float* __restrict__ w128,
                           const float* __restrict__ bv) {
    int o = threadIdx.x;
    float s = 0.f;
    #pragma unroll 8
    for (int c = 0; c < 256; c++) s += w128[o * 256 + c] * bv[c];
    g_pb2[o] = s;
}

// ===========================================================================
// Merged converts. z<16: x [b][c][hw] -> g_Xh [n][c] fp16, 32(hw) x 64(c)
// tiles with half2 (128B/warp) stores.  z==16: wq/wk -> fp16 [o][c].
// grid (32, 4, 17), 256 threads.
// ===========================================================================
__global__ void convert_kernel(const float* __restrict__ x4,
                               const float* __restrict__ x3,
                               const float* __restrict__ wq,
                               const float* __restrict__ wk) {
    int z = blockIdx.z;
    int t = threadIdx.x;
    if (z == 16) {
        int bid = blockIdx.y * 32 + blockIdx.x;   // 0..127
        int e = bid * 1024 + t;
        #pragma unroll
        for (int i = 0; i < 4; i++, e += 256) {
            int o = e >> 8, cc = e & 255;
            float v = (o < 256) ? wq[o * 256 + cc] : wk[(o - 256) * 256 + cc];
            g_Whqk[e] = __float2half_rn(v);
        }
        return;
    }
    __shared__ float tile[64][33];
    int side = z >> 3, b = z & 7;
    const float* x = (side ? x3 : x4) + b * CDIM * HW;
    int hw0 = blockIdx.x * 32;
    int c0 = blockIdx.y * 64;
    int lane = t & 31, ty = t >> 5;

    #pragma unroll
    for (int i = 0; i < 8; i++) {
        int cc = ty + i * 8;
        tile[cc][lane] = x[(c0 + cc) * HW + hw0 + lane];
    }
    __syncthreads();
    int nbase = side * NSIDE + b * HW + hw0;
    #pragma unroll
    for (int i = 0; i < 4; i++) {
        int hwr = ty + i * 8;
        __half2 h = __floats2half2_rn(tile[lane * 2][hwr], tile[lane * 2 + 1][hwr]);
        *(__half2*)&g_Xh[(size_t)(nbase + hwr) * 256 + c0 + lane * 2] = h;
    }
}

// ===========================================================================
// QK fp16 tensor GEMM, 128x64 CTA tile, 2 CTAs/SM.
// ===========================================================================
#define QKG_SMEM ((128 + 64) * 264 * 2)   // 101376 B

__global__ void __launch_bounds__(256, 2) qk_gemm_kernel(const float* __restrict__ bq,
                                                         const float* __restrict__ bk) {
    extern __shared__ __half smh[];
    __half* Xs = smh;                 // 128 x 264
    __half* Ws = smh + 128 * 264;     // 64 x 264
    int t = threadIdx.x, lane = t & 31, wid = t >> 5;
    int wm = wid >> 1, wn = wid & 1;
    int grp = lane >> 2, qid = lane & 3;
    int m0 = blockIdx.x * 128;
    int ob = blockIdx.y;

    uint32_t xb = smem_u32(Xs), wb = smem_u32(Ws);
    #pragma unroll
    for (int i = 0; i < 24; i++) {
        int s = t + i * 256;
        int row = s >> 5, seg = s & 31;
        if (row < 128)
            cp_async16(xb + row * 528 + seg * 16,
                       (const char*)&g_Xh[(size_t)(m0 + row) * 256] + seg * 16);
        else
            cp_async16(wb + (row - 128) * 528 + seg * 16,
                       (const char*)&g_Whqk[(size_t)(ob * 64 + row - 128) * 256] + seg * 16);
    }
    CP_COMMIT(); CP_WAIT(0);
    __syncthreads();

    float acc[2][4][4] = {};
    #pragma unroll
    for (int kk = 0; kk < 16; kk++) {
        uint32_t a[2][4];
        #pragma unroll
        for (int rt = 0; rt < 2; rt++) {
            const __half* q0 = &Xs[(wm * 32 + rt * 16 + grp) * 264 + kk * 16 + qid * 2];
            a[rt][0] = *(const uint32_t*)q0;
            a[rt][1] = *(const uint32_t*)(q0 + 8 * 264);
            a[rt][2] = *(const uint32_t*)(q0 + 8);
            a[rt][3] = *(const uint32_t*)(q0 + 8 * 264 + 8);
        }
        #pragma unroll
        for (int nt = 0; nt < 4; nt++) {
            const __half* kp = &Ws[(wn * 32 + nt * 8 + grp) * 264 + kk * 16 + qid * 2];
            uint32_t b0 = *(const uint32_t*)kp;
            uint32_t b1 = *(const uint32_t*)(kp + 8);
            #pragma unroll
            for (int rt = 0; rt < 2; rt++)
                mma_fp16(acc[rt][nt], a[rt], b0, b1);
        }
    }

    bool isQ = (ob < 4);
    __half* dst = isQ ? g_Qh : g_Kh;
    const float* bias = isQ ? bq : bk;
    #pragma unroll
    for (int rt = 0; rt < 2; rt++)
        #pragma unroll
        for (int nt = 0; nt < 4; nt++) {
            int col = (ob & 3) * 64 + wn * 32 + nt * 8 + qid * 2;
            float b0f = bias[col], b1f = bias[col + 1];
            int r0 = m0 + wm * 32 + rt * 16 + grp;
            __half2 h0 = __floats2half2_rn(acc[rt][nt][0] + b0f, acc[rt][nt][1] + b1f);
            __half2 h1 = __floats2half2_rn(acc[rt][nt][2] + b0f, acc[rt][nt][3] + b1f);
            *(__half2*)&dst[(size_t)r0 * 256 + col] = h0;
            *(__half2*)&dst[(size_t)(r0 + 8) * 256 + col] = h1;
        }
}

// ===========================================================================
// fp16 tensor-core S block-max: 4 warps, warp tile 64x64; pair-scoped K
// loading + named pair barriers (unchanged from R14 — proven).
// ===========================================================================
#define SMAX_SMEM (65536 + 3 * 16384)   // 114688 B -> 2 CTAs/SM

__device__ __forceinline__ void load_k_half(uint32_t kb, int jbase, int c,
                                            int wc, int pt) {
    int jc = c >> 2, kc = c & 3;
    const __half* src = &g_Kh[(size_t)(jbase + jc * 128) * 256 + kc * 64];
    #pragma unroll
    for (int i = 0; i < 8; i++) {
        int idx = pt + i * 64;            // 512 16B segments per half
        int row = wc * 64 + (idx >> 3), seg = idx & 7;
        cp_async16(kb + (uint32_t)(row * 128 + ((seg ^ (row & 7)) * 16)),
                   (const char*)(src + row * 256) + seg * 16);
    }
    CP_COMMIT();
}

__global__ void __launch_bounds__(128, 2) smax_kernel() {
    extern __shared__ char sm[];
    uint32_t qbase = smem_u32(sm);
    uint32_t kbase = qbase + 65536;
    float* red = (float*)(sm + 65536);    // overlaps buffers (used after loop)

    int t = threadIdx.x, lane = t & 31, wid = t >> 5;
    int wr = wid >> 1, wc = wid & 1;      // 2 row-groups x 2 key-halves
    int grp = lane >> 2, qid = lane & 3;
    int pt = wr * 32 + lane;              // index within pair [0,64)
    int i0 = blockIdx.x * 128, kb = blockIdx.y, jbase = kb * HW;

    // Q tile -> smem, swizzled (all threads), then pair K-half prologue
    #pragma unroll
    for (int i = 0; i < 32; i++) {
        int idx = t + i * 128;
        int row = idx >> 5, seg = idx & 31;
        int seg2 = (seg & 24) | ((seg & 7) ^ (row & 7));
        cp_async16(qbase + (uint32_t)(row * 512 + seg2 * 16),
                   (const char*)&g_Qh[(size_t)(i0 + row) * 256] + seg * 16);
    }
    CP_COMMIT();
    load_k_half(kbase + 0 * 16384, jbase, 0, wc, pt);
    load_k_half(kbase + 1 * 16384, jbase, 1, wc, pt);
    CP_WAIT(2);            // Q complete for this thread
    __syncthreads();       // Q complete CTA-wide

    int sw = lane & 7;
    int hi = lane >> 4;
    int lo8 = (lane >> 3) & 1;
    uint32_t qbA = qbase + (uint32_t)((wr * 64 + (lane & 15)) * 512);
    uint32_t kbB = (uint32_t)((wc * 64 + hi * 8 + sw) * 128);
    uint32_t offA[4], offB[4];
    #pragma unroll
    for (int s = 0; s < 4; s++) {
        offA[s] = (uint32_t)(((s * 2 + hi) ^ sw) * 16);
        offB[s] = (uint32_t)(((s * 2 + lo8) ^ sw) * 16);
    }

    float rmax[4][2] = {{-1e30f, -1e30f}, {-1e30f, -1e30f},
                        {-1e30f, -1e30f}, {-1e30f, -1e30f}};
    float acc[4][8][4];
    int barid = 1 + wc;

    for (int c = 0; c < 32; c++) {
        if (c < 31) { CP_WAIT(1); } else { CP_WAIT(0); }
        asm volatile("bar.sync %0, 64;" :: "r"(barid) : "memory");
        if (c + 2 < 32)
            load_k_half(kbase + (uint32_t)((c + 2) % 3) * 16384, jbase, c + 2, wc, pt);

        int kc = c & 3;
        uint32_t kbuf = kbase + (uint32_t)(c % 3) * 16384 + kbB;
        uint32_t qA = qbA + (uint32_t)(kc * 128);

        if (kc == 0) {
            #pragma unroll
            for (int rt = 0; rt < 4; rt++)
                #pragma unroll
                for (int nt = 0; nt < 8; nt++)
                    #pragma unroll
                    for (int r = 0; r < 4; r++) acc[rt][nt][r] = 0.f;
        }

        #pragma unroll
        for (int s = 0; s < 4; s++) {
            uint32_t a[4][4];
            #pragma unroll
            for (int rt = 0; rt < 4; rt++)
                ldsm_x4(a[rt], qA + (uint32_t)(rt * 8192) + offA[s]);
            #pragma unroll
            for (int nt2 = 0; nt2 < 4; nt2++) {
                uint32_t bquad[4];
                ldsm_x4(bquad, kbuf + (uint32_t)(nt2 * 2048) + offB[s]);
                #pragma unroll
                for (int rt = 0; rt < 4; rt++) {
                    mma_fp16(acc[rt][nt2 * 2 + 0], a[rt], bquad[0], bquad[1]);
                    mma_fp16(acc[rt][nt2 * 2 + 1], a[rt], bquad[2], bquad[3]);
                }
            }
        }

        if (kc == 3) {
            #pragma unroll
            for (int rt = 0; rt < 4; rt++)
                #pragma unroll
                for (int nt = 0; nt < 8; nt++) {
                    rmax[rt][0] = fmaxf(rmax[rt][0], fmaxf(acc[rt][nt][0], acc[rt][nt][1]));
                    rmax[rt][1] = fmaxf(rmax[rt][1], fmaxf(acc[rt][nt][2], acc[rt][nt][3]));
                }
        }
    }

    #pragma unroll
    for (int rt = 0; rt < 4; rt++)
        #pragma unroll
        for (int h = 0; h < 2; h++) {
            float v = rmax[rt][h];
            v = fmaxf(v, __shfl_xor_sync(0xFFFFFFFF, v, 1));
            v = fmaxf(v, __shfl_xor_sync(0xFFFFFFFF, v, 2));
            rmax[rt][h] = v;
        }

    __syncthreads();     // all pairs done with buffers before red overlay
    if (qid == 0) {
        #pragma unroll
        for (int rt = 0; rt < 4; rt++)
            #pragma unroll
            for (int h = 0; h < 2; h++) {
                int row = wr * 64 + rt * 16 + h * 8 + grp;
                red[wc * 128 + row] = rmax[rt][h];
            }
    }
    __syncthreads();
    if (t < 128)
        g_BM[(i0 + t) * 16 + kb] = fmaxf(red[t], red[128 + t]);
}

// ===========================================================================
// Gate: softmax over 1024 of mean-of-8-blockmax * scale (float4 BM reads)
// ===========================================================================
__global__ void gate_kernel() {
    int g = blockIdx.x >> 3;
    int b = blockIdx.x & 7;
    int side = (g == 0 || g == 2) ? 0 : 1;
    int kbb  = (g == 0 || g == 3) ? 0 : 8;
    int irow = side * NSIDE + b * HW;
    int t = threadIdx.x;

    float vals[4];
    #pragma unroll
    for (int r = 0; r < 4; r++) {
        int hw = t + 256 * r;
        const float4* bm = (const float4*)&g_BM[(irow + hw) * 16 + kbb];
        float4 v0 = bm[0], v1 = bm[1];
        vals[r] = ((v0.x + v0.y) + (v0.z + v0.w) + (v1.x + v1.y) + (v1.z + v1.w))
                  * (0.0625f / 8.0f);
    }
    __shared__ float red[256];
    float mx = fmaxf(fmaxf(vals[0], vals[1]), fmaxf(vals[2], vals[3]));
    red[t] = mx; __syncthreads();
    for (int s2 = 128; s2 > 0; s2 >>= 1) {
        if (t < s2) red[t] = fmaxf(red[t], red[t + s2]);
        __syncthreads();
    }
    mx = red[0]; __syncthreads();
    float sum = 0.f;
    #pragma unroll
    for (int r = 0; r < 4; r++) { vals[r] = expf(vals[r] - mx); sum += vals[r]; }
    red[t] = sum; __syncthreads();
    for (int s2 = 128; s2 > 0; s2 >>= 1) {
        if (t < s2) red[t] += red[t + s2];
        __syncthreads();
    }
    float inv = 1.f / red[0];
    #pragma unroll
    for (int r = 0; r < 4; r++)
        g_GW[g * NSIDE + b * HW + t + 256 * r] = vals[r] * inv;
}

// ===========================================================================
// Fused projection: P[o][n] = sum_c wcT[c][o] * x[.][c][hw] + pb2[o]
// 64x64 tiles (R14 version — proven best interleaving with smax).
// ===========================================================================
__global__ void pcomb_kernel(const float* __restrict__ x4,
                             const float* __restrict__ x3) {
    int n0 = blockIdx.x * 64;
    int side = n0 >> 13;
    int rem = n0 & (NSIDE - 1);
    int b = rem >> 10;
    int hw0 = rem & (HW - 1);
    const float* x = (side ? x3 : x4) + b * CDIM * HW;
    int o0 = blockIdx.y * 64;

    __shared__ float Xs[16][64];
    __shared__ float Ws[16][64];
    int t = threadIdx.x;
    int tx = t & 15, ty = t >> 4;
    float acc[4][4] = {};

    for (int c0 = 0; c0 < CDIM; c0 += 16) {
        #pragma unroll
        for (int r = 0; r < 4; r++) {
            int idx = r * 256 + t;
            int cc = idx >> 6, nn = idx & 63;
            Xs[cc][nn] = x[(c0 + cc) * HW + hw0 + nn];
            Ws[cc][nn] = g_wcT[(c0 + cc) * 128 + o0 + nn];
        }
        __syncthreads();
        #pragma unroll
        for (int kk = 0; kk < 16; kk++) {
            float4 o4 = *(const float4*)&Ws[kk][ty * 4];
            float4 n4 = *(const float4*)&Xs[kk][tx * 4];
            float oo[4] = {o4.x, o4.y, o4.z, o4.w};
            float nn[4] = {n4.x, n4.y, n4.z, n4.w};
            #pragma unroll
            for (int r = 0; r < 4; r++)
                #pragma unroll
                for (int c2 = 0; c2 < 4; c2++)
                    acc[r][c2] += oo[r] * nn[c2];
        }
        __syncthreads();
    }
    #pragma unroll
    for (int r = 0; r < 4; r++) {
        int o = o0 + ty * 4 + r;
        float pb = g_pb2[o];
        float4 v;
        v.x = acc[r][0] + pb; v.y = acc[r][1] + pb;
        v.z = acc[r][2] + pb; v.w = acc[r][3] + pb;
        *(float4*)&g_P[o * NTOT + n0 + tx * 4] = v;
    }
}

// ===========================================================================
// Final: out = gate * P + b128; one thread serves the two channels sharing P.
// ===========================================================================
__global__ void final_kernel(const float* __restrict__ b128, float* __restrict__ out) {
    int idx4 = (blockIdx.x * 256 + threadIdx.x) * 4;
    int hw = idx4 & (HW - 1);
    int o = (idx4 >> 10) & 127;
    int rest = idx4 >> 17;
    int pside = rest & 1;
    int b = rest >> 1;
    int n = b * HW + hw;

    int gA = pside ? 2 : 3;
    int gB = pside ? 1 : 0;
    int brA = pside * 2, brB = pside * 2 + 1;

    float4 pv = *(const float4*)&g_P[(size_t)o * NTOT + pside * NSIDE + n];
    float4 ga = *(const float4*)&g_GW[gA * NSIDE + n];
    float4 gb = *(const float4*)&g_GW[gB * NSIDE + n];
    float bb = b128[o];

    float4 oa, ob;
    oa.x = ga.x * pv.x + bb; oa.y = ga.y * pv.y + bb;
    oa.z = ga.z * pv.z + bb; oa.w = ga.w * pv.w + bb;
    ob.x = gb.x * pv.x + bb; ob.y = gb.y * pv.y + bb;
    ob.z = gb.z * pv.z + bb; ob.w = gb.w * pv.w + bb;

    size_t obase = (size_t)b * 524288 + hw;
    *(float4*)&out[obase + (size_t)(brA * 128 + o) * 1024] = oa;
    *(float4*)&out[obase + (size_t)(brB * 128 + o) * 1024] = ob;
}

extern "C" void kernel_launch(void* const* d_in, const int* in_sizes, int n_in,
                              void* d_out, int out_size) {
    const float* x4   = (const float*)d_in[0];
    const float* x3   = (const float*)d_in[1];
    const float* wq   = (const float*)d_in[2];
    const float* bq   = (const float*)d_in[3];
    const float* wk   = (const float*)d_in[4];
    const float* bk   = (const float*)d_in[5];
    const float* wv   = (const float*)d_in[6];
    const float* bv   = (const float*)d_in[7];
    const float* w128 = (const float*)d_in[8];
    const float* b128 = (const float*)d_in[9];
    float* out = (float*)d_out;

    static cudaStream_t s2 = nullptr;
    static cudaEvent_t evFork = nullptr, evJoin = nullptr;
    if (!s2) {
        cudaFuncSetAttribute(smax_kernel,
                             cudaFuncAttributeMaxDynamicSharedMemorySize, SMAX_SMEM);
        cudaFuncSetAttribute(qk_gemm_kernel,
                             cudaFuncAttributeMaxDynamicSharedMemorySize, QKG_SMEM);
        cudaStreamCreateWithFlags(&s2, cudaStreamNonBlocking);
        cudaEventCreateWithFlags(&evFork, cudaEventDisableTiming);
        cudaEventCreateWithFlags(&evJoin, cudaEventDisableTiming);
    }

    // fork: independent projection branch runs concurrently with the QK chain
    cudaEventRecord(evFork, 0);
    cudaStreamWaitEvent(s2, evFork, 0);
    combine_w_kernel<<<256, 128, 0, s2>>>(w128, wv);
    pb2_kernel<<<1, 128, 0, s2>>>(w128, bv);
    pcomb_kernel<<<dim3(256, 2), 256, 0, s2>>>(x4, x3);
    cudaEventRecord(evJoin, s2);

    // main chain
    convert_kernel<<<dim3(32, 4, 17), 256>>>(x4, x3, wq, wk);
    qk_gemm_kernel<<<dim3(128, 8), 256, QKG_SMEM>>>(bq, bk);
    smax_kernel<<<dim3(128, 16), 128, SMAX_SMEM>>>();
    gate_kernel<<<32, 256>>>();
    cudaStreamWaitEvent(0, evJoin, 0);
    final_kernel<<<2048, 256>>>(b128, out);
}

// round 17
// speedup vs baseline: 1.0103x; 1.0033x over previous
#include <cuda_runtime.h>
#include <cuda_fp16.h>
#include <cstdint>

#define HW 1024
#define CDIM 256
#define NSIDE 8192
#define NTOT 16384

// -------- scratch (device globals; no allocation allowed) --------
__device__ __half g_Xh[NTOT * CDIM];      // x transposed to [n][c], fp16
__device__ __half g_Whqk[512 * CDIM];     // [wq;wk] as [o][c], fp16
__device__ __half g_Qh[NTOT * CDIM];
__device__ __half g_Kh[NTOT * CDIM];
__device__ float  g_wcT[CDIM * 128];      // (w128 @ wv) transposed [c][o]
__device__ float  g_pb2[128];             // w128 @ bv
__device__ float  g_BM[NTOT * 16];
__device__ float  g_GW[4 * NSIDE];
__device__ float  g_P[128 * NTOT];

// ======================= helpers =======================
__device__ __forceinline__ uint32_t smem_u32(const void* p) {
    uint32_t a;
    asm("{ .reg .u64 t; cvta.to.shared.u64 t, %1; cvt.u32.u64 %0, t; }"
        : "=r"(a) : "l"(p));
    return a;
}
__device__ __forceinline__ void cp_async16(uint32_t dst, const void* src) {
    asm volatile("cp.async.cg.shared.global [%0], [%1], 16;" :: "r"(dst), "l"(src) : "memory");
}
#define CP_COMMIT() asm volatile("cp.async.commit_group;" ::: "memory")
#define CP_WAIT(n)  asm volatile("cp.async.wait_group %0;" :: "n"(n) : "memory")

__device__ __forceinline__ void mma_fp16(float* c, const uint32_t* a,
                                         uint32_t b0, uint32_t b1) {
    asm volatile(
        "mma.sync.aligned.m16n8k16.row.col.f32.f16.f16.f32 "
        "{%0,%1,%2,%3}, {%4,%5,%6,%7}, {%8,%9}, {%0,%1,%2,%3};"
        : "+f"(c[0]), "+f"(c[1]), "+f"(c[2]), "+f"(c[3])
        : "r"(a[0]), "r"(a[1]), "r"(a[2]), "r"(a[3]), "r"(b0), "r"(b1));
}
__device__ __forceinline__ void ldsm_x4(uint32_t* r, uint32_t addr) {
    asm volatile("ldmatrix.sync.aligned.m8n8.x4.shared.b16 {%0,%1,%2,%3}, [%4];"
        : "=r"(r[0]), "=r"(r[1]), "=r"(r[2]), "=r"(r[3]) : "r"(addr));
}

// ===========================================================================
// wcombT[c][o] = sum_k w128[o][k] * wv[k][c]
// ===========================================================================
__global__ void combine_w_kernel(const float* __restrict__ w128,
                                 const float* __restrict__ wv) {
    int c = blockIdx.x, o = threadIdx.x;
    float s = 0.f;
    #pragma unroll 8
    for (int k = 0; k < 256; k++)
        s += w128[o * 256 + k] * wv[k * 256 + c];
    g_wcT[c * 128 + o] = s;
}

__global__ void pb2_kernel(const float* __restrict__ w128,
                           const float* __restrict__ bv) {
    int o = threadIdx.x;
    float s = 0.f;
    #pragma unroll 8
    for (int c = 0; c < 256; c++) s += w128[o * 256 + c] * bv[c];
    g_pb2[o] = s;
}

// ===========================================================================
// Merged converts. z<16: x [b][c][hw] -> g_Xh [n][c] fp16, 32(hw) x 64(c)
// tiles with half2 (128B/warp) stores.  z==16: wq/wk -> fp16 [o][c].
// ===========================================================================
__global__ void convert_kernel(const float* __restrict__ x4,
                               const float* __restrict__ x3,
                               const float* __restrict__ wq,
                               const float* __restrict__ wk) {
    int z = blockIdx.z;
    int t = threadIdx.x;
    if (z == 16) {
        int bid = blockIdx.y * 32 + blockIdx.x;   // 0..127
        int e = bid * 1024 + t;
        #pragma unroll
        for (int i = 0; i < 4; i++, e += 256) {
            int o = e >> 8, cc = e & 255;
            float v = (o < 256) ? wq[o * 256 + cc] : wk[(o - 256) * 256 + cc];
            g_Whqk[e] = __float2half_rn(v);
        }
        return;
    }
    __shared__ float tile[64][33];
    int side = z >> 3, b = z & 7;
    const float* x = (side ? x3 : x4) + b * CDIM * HW;
    int hw0 = blockIdx.x * 32;
    int c0 = blockIdx.y * 64;
    int lane = t & 31, ty = t >> 5;

    #pragma unroll
    for (int i = 0; i < 8; i++) {
        int cc = ty + i * 8;
        tile[cc][lane] = x[(c0 + cc) * HW + hw0 + lane];
    }
    __syncthreads();
    int nbase = side * NSIDE + b * HW + hw0;
    #pragma unroll
    for (int i = 0; i < 4; i++) {
        int hwr = ty + i * 8;
        __half2 h = __floats2half2_rn(tile[lane * 2][hwr], tile[lane * 2 + 1][hwr]);
        *(__half2*)&g_Xh[(size_t)(nbase + hwr) * 256 + c0 + lane * 2] = h;
    }
}

// ===========================================================================
// QK fp16 tensor GEMM, 128x64 CTA tile, 2 CTAs/SM.
// ===========================================================================
#define QKG_SMEM ((128 + 64) * 264 * 2)   // 101376 B

__global__ void __launch_bounds__(256, 2) qk_gemm_kernel(const float* __restrict__ bq,
                                                         const float* __restrict__ bk) {
    extern __shared__ __half smh[];
    __half* Xs = smh;                 // 128 x 264
    __half* Ws = smh + 128 * 264;     // 64 x 264
    int t = threadIdx.x, lane = t & 31, wid = t >> 5;
    int wm = wid >> 1, wn = wid & 1;
    int grp = lane >> 2, qid = lane & 3;
    int m0 = blockIdx.x * 128;
    int ob = blockIdx.y;

    uint32_t xb = smem_u32(Xs), wb = smem_u32(Ws);
    #pragma unroll
    for (int i = 0; i < 24; i++) {
        int s = t + i * 256;
        int row = s >> 5, seg = s & 31;
        if (row < 128)
            cp_async16(xb + row * 528 + seg * 16,
                       (const char*)&g_Xh[(size_t)(m0 + row) * 256] + seg * 16);
        else
            cp_async16(wb + (row - 128) * 528 + seg * 16,
                       (const char*)&g_Whqk[(size_t)(ob * 64 + row - 128) * 256] + seg * 16);
    }
    CP_COMMIT(); CP_WAIT(0);
    __syncthreads();

    float acc[2][4][4] = {};
    #pragma unroll
    for (int kk = 0; kk < 16; kk++) {
        uint32_t a[2][4];
        #pragma unroll
        for (int rt = 0; rt < 2; rt++) {
            const __half* q0 = &Xs[(wm * 32 + rt * 16 + grp) * 264 + kk * 16 + qid * 2];
            a[rt][0] = *(const uint32_t*)q0;
            a[rt][1] = *(const uint32_t*)(q0 + 8 * 264);
            a[rt][2] = *(const uint32_t*)(q0 + 8);
            a[rt][3] = *(const uint32_t*)(q0 + 8 * 264 + 8);
        }
        #pragma unroll
        for (int nt = 0; nt < 4; nt++) {
            const __half* kp = &Ws[(wn * 32 + nt * 8 + grp) * 264 + kk * 16 + qid * 2];
            uint32_t b0 = *(const uint32_t*)kp;
            uint32_t b1 = *(const uint32_t*)(kp + 8);
            #pragma unroll
            for (int rt = 0; rt < 2; rt++)
                mma_fp16(acc[rt][nt], a[rt], b0, b1);
        }
    }

    bool isQ = (ob < 4);
    __half* dst = isQ ? g_Qh : g_Kh;
    const float* bias = isQ ? bq : bk;
    #pragma unroll
    for (int rt = 0; rt < 2; rt++)
        #pragma unroll
        for (int nt = 0; nt < 4; nt++) {
            int col = (ob & 3) * 64 + wn * 32 + nt * 8 + qid * 2;
            float b0f = bias[col], b1f = bias[col + 1];
            int r0 = m0 + wm * 32 + rt * 16 + grp;
            __half2 h0 = __floats2half2_rn(acc[rt][nt][0] + b0f, acc[rt][nt][1] + b1f);
            __half2 h1 = __floats2half2_rn(acc[rt][nt][2] + b0f, acc[rt][nt][3] + b1f);
            *(__half2*)&dst[(size_t)r0 * 256 + col] = h0;
            *(__half2*)&dst[(size_t)(r0 + 8) * 256 + col] = h1;
        }
}

// ===========================================================================
// fp16 tensor-core S block-max: 4 warps, warp tile 64x64; pair-scoped K
// loading + named pair barriers (R14 version — proven best).
// ===========================================================================
#define SMAX_SMEM (65536 + 3 * 16384)   // 114688 B -> 2 CTAs/SM

__device__ __forceinline__ void load_k_half(uint32_t kb, int jbase, int c,
                                            int wc, int pt) {
    int jc = c >> 2, kc = c & 3;
    const __half* src = &g_Kh[(size_t)(jbase + jc * 128) * 256 + kc * 64];
    #pragma unroll
    for (int i = 0; i < 8; i++) {
        int idx = pt + i * 64;            // 512 16B segments per half
        int row = wc * 64 + (idx >> 3), seg = idx & 7;
        cp_async16(kb + (uint32_t)(row * 128 + ((seg ^ (row & 7)) * 16)),
                   (const char*)(src + row * 256) + seg * 16);
    }
    CP_COMMIT();
}

__global__ void __launch_bounds__(128, 2) smax_kernel() {
    extern __shared__ char sm[];
    uint32_t qbase = smem_u32(sm);
    uint32_t kbase = qbase + 65536;
    float* red = (float*)(sm + 65536);    // overlaps buffers (used after loop)

    int t = threadIdx.x, lane = t & 31, wid = t >> 5;
    int wr = wid >> 1, wc = wid & 1;      // 2 row-groups x 2 key-halves
    int grp = lane >> 2, qid = lane & 3;
    int pt = wr * 32 + lane;              // index within pair [0,64)
    int i0 = blockIdx.x * 128, kb = blockIdx.y, jbase = kb * HW;

    // Q tile -> smem, swizzled (all threads), then pair K-half prologue
    #pragma unroll
    for (int i = 0; i < 32; i++) {
        int idx = t + i * 128;
        int row = idx >> 5, seg = idx & 31;
        int seg2 = (seg & 24) | ((seg & 7) ^ (row & 7));
        cp_async16(qbase + (uint32_t)(row * 512 + seg2 * 16),
                   (const char*)&g_Qh[(size_t)(i0 + row) * 256] + seg * 16);
    }
    CP_COMMIT();
    load_k_half(kbase + 0 * 16384, jbase, 0, wc, pt);
    load_k_half(kbase + 1 * 16384, jbase, 1, wc, pt);
    CP_WAIT(2);            // Q complete for this thread
    __syncthreads();       // Q complete CTA-wide

    int sw = lane & 7;
    int hi = lane >> 4;
    int lo8 = (lane >> 3) & 1;
    uint32_t qbA = qbase + (uint32_t)((wr * 64 + (lane & 15)) * 512);
    uint32_t kbB = (uint32_t)((wc * 64 + hi * 8 + sw) * 128);
    uint32_t offA[4], offB[4];
    #pragma unroll
    for (int s = 0; s < 4; s++) {
        offA[s] = (uint32_t)(((s * 2 + hi) ^ sw) * 16);
        offB[s] = (uint32_t)(((s * 2 + lo8) ^ sw) * 16);
    }

    float rmax[4][2] = {{-1e30f, -1e30f}, {-1e30f, -1e30f},
                        {-1e30f, -1e30f}, {-1e30f, -1e30f}};
    float acc[4][8][4];
    int barid = 1 + wc;

    for (int c = 0; c < 32; c++) {
        if (c < 31) { CP_WAIT(1); } else { CP_WAIT(0); }
        asm volatile("bar.sync %0, 64;" :: "r"(barid) : "memory");
        if (c + 2 < 32)
            load_k_half(kbase + (uint32_t)((c + 2) % 3) * 16384, jbase, c + 2, wc, pt);

        int kc = c & 3;
        uint32_t kbuf = kbase + (uint32_t)(c % 3) * 16384 + kbB;
        uint32_t qA = qbA + (uint32_t)(kc * 128);

        if (kc == 0) {
            #pragma unroll
            for (int rt = 0; rt < 4; rt++)
                #pragma unroll
                for (int nt = 0; nt < 8; nt++)
                    #pragma unroll
                    for (int r = 0; r < 4; r++) acc[rt][nt][r] = 0.f;
        }

        #pragma unroll
        for (int s = 0; s < 4; s++) {
            uint32_t a[4][4];
            #pragma unroll
            for (int rt = 0; rt < 4; rt++)
                ldsm_x4(a[rt], qA + (uint32_t)(rt * 8192) + offA[s]);
            #pragma unroll
            for (int nt2 = 0; nt2 < 4; nt2++) {
                uint32_t bquad[4];
                ldsm_x4(bquad, kbuf + (uint32_t)(nt2 * 2048) + offB[s]);
                #pragma unroll
                for (int rt = 0; rt < 4; rt++) {
                    mma_fp16(acc[rt][nt2 * 2 + 0], a[rt], bquad[0], bquad[1]);
                    mma_fp16(acc[rt][nt2 * 2 + 1], a[rt], bquad[2], bquad[3]);
                }
            }
        }

        if (kc == 3) {
            #pragma unroll
            for (int rt = 0; rt < 4; rt++)
                #pragma unroll
                for (int nt = 0; nt < 8; nt++) {
                    rmax[rt][0] = fmaxf(rmax[rt][0], fmaxf(acc[rt][nt][0], acc[rt][nt][1]));
                    rmax[rt][1] = fmaxf(rmax[rt][1], fmaxf(acc[rt][nt][2], acc[rt][nt][3]));
                }
        }
    }

    #pragma unroll
    for (int rt = 0; rt < 4; rt++)
        #pragma unroll
        for (int h = 0; h < 2; h++) {
            float v = rmax[rt][h];
            v = fmaxf(v, __shfl_xor_sync(0xFFFFFFFF, v, 1));
            v = fmaxf(v, __shfl_xor_sync(0xFFFFFFFF, v, 2));
            rmax[rt][h] = v;
        }

    __syncthreads();     // all pairs done with buffers before red overlay
    if (qid == 0) {
        #pragma unroll
        for (int rt = 0; rt < 4; rt++)
            #pragma unroll
            for (int h = 0; h < 2; h++) {
                int row = wr * 64 + rt * 16 + h * 8 + grp;
                red[wc * 128 + row] = rmax[rt][h];
            }
    }
    __syncthreads();
    if (t < 128)
        g_BM[(i0 + t) * 16 + kb] = fmaxf(red[t], red[128 + t]);
}

// ===========================================================================
// Gate: softmax over 1024 of mean-of-8-blockmax * scale.
// Warp-shuffle reductions (2 __syncthreads total instead of 16).
// ===========================================================================
__global__ void gate_kernel() {
    int g = blockIdx.x >> 3;
    int b = blockIdx.x & 7;
    int side = (g == 0 || g == 2) ? 0 : 1;
    int kbb  = (g == 0 || g == 3) ? 0 : 8;
    int irow = side * NSIDE + b * HW;
    int t = threadIdx.x;
    int lane = t & 31, wid = t >> 5;

    float vals[4];
    #pragma unroll
    for (int r = 0; r < 4; r++) {
        int hw = t + 256 * r;
        const float4* bm = (const float4*)&g_BM[(irow + hw) * 16 + kbb];
        float4 v0 = bm[0], v1 = bm[1];
        vals[r] = ((v0.x + v0.y) + (v0.z + v0.w) + (v1.x + v1.y) + (v1.z + v1.w))
                  * (0.0625f / 8.0f);
    }

    __shared__ float redm[8], reds[8];
    // --- max ---
    float mx = fmaxf(fmaxf(vals[0], vals[1]), fmaxf(vals[2], vals[3]));
    #pragma unroll
    for (int d = 16; d > 0; d >>= 1)
        mx = fmaxf(mx, __shfl_xor_sync(0xFFFFFFFF, mx, d));
    if (lane == 0) redm[wid] = mx;
    __syncthreads();
    mx = redm[0];
    #pragma unroll
    for (int w = 1; w < 8; w++) mx = fmaxf(mx, redm[w]);

    // --- sum of exp ---
    float sum = 0.f;
    #pragma unroll
    for (int r = 0; r < 4; r++) { vals[r] = expf(vals[r] - mx); sum += vals[r]; }
    #pragma unroll
    for (int d = 16; d > 0; d >>= 1)
        sum += __shfl_xor_sync(0xFFFFFFFF, sum, d);
    if (lane == 0) reds[wid] = sum;
    __syncthreads();
    sum = reds[0];
    #pragma unroll
    for (int w = 1; w < 8; w++) sum += reds[w];

    float inv = 1.f / sum;
    #pragma unroll
    for (int r = 0; r < 4; r++)
        g_GW[g * NSIDE + b * HW + t + 256 * r] = vals[r] * inv;
}

// ===========================================================================
// Fused projection: P[o][n] = sum_c wcT[c][o] * x[.][c][hw] + pb2[o]
// 64x64 tiles (R14 version — proven best interleaving with smax).
// ===========================================================================
__global__ void pcomb_kernel(const float* __restrict__ x4,
                             const float* __restrict__ x3) {
    int n0 = blockIdx.x * 64;
    int side = n0 >> 13;
    int rem = n0 & (NSIDE - 1);
    int b = rem >> 10;
    int hw0 = rem & (HW - 1);
    const float* x = (side ? x3 : x4) + b * CDIM * HW;
    int o0 = blockIdx.y * 64;

    __shared__ float Xs[16][64];
    __shared__ float Ws[16][64];
    int t = threadIdx.x;
    int tx = t & 15, ty = t >> 4;
    float acc[4][4] = {};

    for (int c0 = 0; c0 < CDIM; c0 += 16) {
        #pragma unroll
        for (int r = 0; r < 4; r++) {
            int idx = r * 256 + t;
            int cc = idx >> 6, nn = idx & 63;
            Xs[cc][nn] = x[(c0 + cc) * HW + hw0 + nn];
            Ws[cc][nn] = g_wcT[(c0 + cc) * 128 + o0 + nn];
        }
        __syncthreads();
        #pragma unroll
        for (int kk = 0; kk < 16; kk++) {
            float4 o4 = *(const float4*)&Ws[kk][ty * 4];
            float4 n4 = *(const float4*)&Xs[kk][tx * 4];
            float oo[4] = {o4.x, o4.y, o4.z, o4.w};
            float nn[4] = {n4.x, n4.y, n4.z, n4.w};
            #pragma unroll
            for (int r = 0; r < 4; r++)
                #pragma unroll
                for (int c2 = 0; c2 < 4; c2++)
                    acc[r][c2] += oo[r] * nn[c2];
        }
        __syncthreads();
    }
    #pragma unroll
    for (int r = 0; r < 4; r++) {
        int o = o0 + ty * 4 + r;
        float pb = g_pb2[o];
        float4 v;
        v.x = acc[r][0] + pb; v.y = acc[r][1] + pb;
        v.z = acc[r][2] + pb; v.w = acc[r][3] + pb;
        *(float4*)&g_P[o * NTOT + n0 + tx * 4] = v;
    }
}

// ===========================================================================
// Final: out = gate * P + b128; one thread serves the two channels sharing P.
// ===========================================================================
__global__ void final_kernel(const float* __restrict__ b128, float* __restrict__ out) {
    int idx4 = (blockIdx.x * 256 + threadIdx.x) * 4;
    int hw = idx4 & (HW - 1);
    int o = (idx4 >> 10) & 127;
    int rest = idx4 >> 17;
    int pside = rest & 1;
    int b = rest >> 1;
    int n = b * HW + hw;

    int gA = pside ? 2 : 3;
    int gB = pside ? 1 : 0;
    int brA = pside * 2, brB = pside * 2 + 1;

    float4 pv = *(const float4*)&g_P[(size_t)o * NTOT + pside * NSIDE + n];
    float4 ga = *(const float4*)&g_GW[gA * NSIDE + n];
    float4 gb = *(const float4*)&g_GW[gB * NSIDE + n];
    float bb = b128[o];

    float4 oa, ob;
    oa.x = ga.x * pv.x + bb; oa.y = ga.y * pv.y + bb;
    oa.z = ga.z * pv.z + bb; oa.w = ga.w * pv.w + bb;
    ob.x = gb.x * pv.x + bb; ob.y = gb.y * pv.y + bb;
    ob.z = gb.z * pv.z + bb; ob.w = gb.w * pv.w + bb;

    size_t obase = (size_t)b * 524288 + hw;
    *(float4*)&out[obase + (size_t)(brA * 128 + o) * 1024] = oa;
    *(float4*)&out[obase + (size_t)(brB * 128 + o) * 1024] = ob;
}

extern "C" void kernel_launch(void* const* d_in, const int* in_sizes, int n_in,
                              void* d_out, int out_size) {
    const float* x4   = (const float*)d_in[0];
    const float* x3   = (const float*)d_in[1];
    const float* wq   = (const float*)d_in[2];
    const float* bq   = (const float*)d_in[3];
    const float* wk   = (const float*)d_in[4];
    const float* bk   = (const float*)d_in[5];
    const float* wv   = (const float*)d_in[6];
    const float* bv   = (const float*)d_in[7];
    const float* w128 = (const float*)d_in[8];
    const float* b128 = (const float*)d_in[9];
    float* out = (float*)d_out;

    static cudaStream_t s2 = nullptr;
    static cudaEvent_t evFork = nullptr, evJoin = nullptr;
    if (!s2) {
        cudaFuncSetAttribute(smax_kernel,
                             cudaFuncAttributeMaxDynamicSharedMemorySize, SMAX_SMEM);
        cudaFuncSetAttribute(qk_gemm_kernel,
                             cudaFuncAttributeMaxDynamicSharedMemorySize, QKG_SMEM);
        cudaStreamCreateWithFlags(&s2, cudaStreamNonBlocking);
        cudaEventCreateWithFlags(&evFork, cudaEventDisableTiming);
        cudaEventCreateWithFlags(&evJoin, cudaEventDisableTiming);
    }

    // fork: independent projection branch runs concurrently with the QK chain
    cudaEventRecord(evFork, 0);
    cudaStreamWaitEvent(s2, evFork, 0);
    combine_w_kernel<<<256, 128, 0, s2>>>(w128, wv);
    pb2_kernel<<<1, 128, 0, s2>>>(w128, bv);
    pcomb_kernel<<<dim3(256, 2), 256, 0, s2>>>(x4, x3);
    cudaEventRecord(evJoin, s2);

    // main chain
    convert_kernel<<<dim3(32, 4, 17), 256>>>(x4, x3, wq, wk);
    qk_gemm_kernel<<<dim3(128, 8), 256, QKG_SMEM>>>(bq, bk);
    smax_kernel<<<dim3(128, 16), 128, SMAX_SMEM>>>();
    gate_kernel<<<32, 256>>>();
    cudaStreamWaitEvent(0, evJoin, 0);
    final_kernel<<<2048, 256>>>(b128, out);
}